// round 1
// baseline (speedup 1.0000x reference)
#include <cuda_runtime.h>
#include <cstdint>

// ---------------- problem constants ----------------
#define TSZ   512
#define NTILE 64          // 8 it * 8 ot
#define NB    1024        // batch
#define ITN   8
#define OTN   8

#define GMIN   1e-6f
#define GDIFF  ((float)(1.0e-4 - 1.0e-6))          // G_MAX - G_MIN (double -> f32, like jnp)
#define STEPQ  ((float)((1.0e-4 - 1.0e-6) / 15.0)) // (G_MAX-G_MIN)/(2^4-1)

// ---------------- scratch (static device memory; no allocations) ----------------
__device__ float g_cond[(size_t)NTILE * TSZ * TSZ];   //  64 MB
__device__ float g_geff[(size_t)NTILE * TSZ * TSZ];   //  64 MB
__device__ float g_cur [(size_t)NTILE * NB * TSZ];    // 128 MB
__device__ float g_idl [(size_t)NTILE * NB * TSZ];    // 128 MB
__device__ float g_s[NTILE], g_wmin[NTILE];
__device__ float g_pmin[NTILE * 8], g_pmax[NTILE * 8];
__device__ float g_xsum[NB * ITN];

// ---------------- f32x2 packed-FMA helpers (Blackwell) ----------------
typedef unsigned long long ull;
__device__ __forceinline__ ull pk2(float lo, float hi) {
    ull r; asm("mov.b64 %0, {%1,%2};" : "=l"(r) : "f"(lo), "f"(hi)); return r;
}
__device__ __forceinline__ float2 up2(ull v) {
    float2 r; asm("mov.b64 {%0,%1}, %2;" : "=f"(r.x), "=f"(r.y) : "l"(v)); return r;
}
__device__ __forceinline__ void fma2(ull& d, ull a, ull b) {
    asm("fma.rn.f32x2 %0, %1, %2, %0;" : "+l"(d) : "l"(a), "l"(b));
}

// ---------------- kernel 1a: per-tile min/max partials ----------------
// grid (8 chunks, 64 tiles), 256 threads
__global__ void k_minmax_part(const float* __restrict__ w) {
    int t = blockIdx.y;            // tile id = it*8 + ot
    int chunk = blockIdx.x;        // 0..7
    int it = t >> 3, ot = t & 7;
    int tid = threadIdx.x;
    float mn = 3.402823466e38f, mx = -3.402823466e38f;
    int base = chunk * 32768 + tid;
    #pragma unroll 4
    for (int k = 0; k < 128; k++) {
        int e = base + k * 256;
        int i = e >> 9, j = e & 511;
        float v = w[(size_t)(it * TSZ + i) * 4096 + ot * TSZ + j];
        mn = fminf(mn, v);
        mx = fmaxf(mx, v);
    }
    __shared__ float smn[256], smx[256];
    smn[tid] = mn; smx[tid] = mx;
    __syncthreads();
    for (int o = 128; o > 0; o >>= 1) {
        if (tid < o) {
            smn[tid] = fminf(smn[tid], smn[tid + o]);
            smx[tid] = fmaxf(smx[tid], smx[tid + o]);
        }
        __syncthreads();
    }
    if (tid == 0) { g_pmin[t * 8 + chunk] = smn[0]; g_pmax[t * 8 + chunk] = smx[0]; }
}

// ---------------- kernel 1b: finalize per-tile scale ----------------
__global__ void k_minmax_fin() {
    int t = threadIdx.x;
    if (t < NTILE) {
        float mn = g_pmin[t * 8], mx = g_pmax[t * 8];
        #pragma unroll
        for (int c = 1; c < 8; c++) {
            mn = fminf(mn, g_pmin[t * 8 + c]);
            mx = fmaxf(mx, g_pmax[t * 8 + c]);
        }
        // s = (G_MAX-G_MIN)/(wmax-wmin+1e-12) -- exact fp32 op order of the reference
        float denom = __fadd_rn(__fsub_rn(mx, mn), 1e-12f);
        g_s[t] = __fdiv_rn(GDIFF, denom);
        g_wmin[t] = mn;
    }
}

// ---------------- kernel 2: build quantized cond and jeong g_eff (bit-exact) ----------------
// 4 elements/thread, 16384 blocks x 256 threads
__global__ void k_build(const float* __restrict__ w) {
    int gid = blockIdx.x * blockDim.x + threadIdx.x;
    int e = gid * 4;                    // element index within [64][512][512]
    int t = e >> 18;
    int r = e & 262143;
    int i = r >> 9;
    int j = r & 511;                    // multiple of 4
    int it = t >> 3, ot = t & 7;
    const float4 w4 = *(const float4*)&w[(size_t)(it * TSZ + i) * 4096 + ot * TSZ + j];
    float s = g_s[t], wmin = g_wmin[t];
    float wv[4] = { w4.x, w4.y, w4.z, w4.w };
    float4 oc, og;
    float* pc = &oc.x; float* pg = &og.x;
    #pragma unroll
    for (int l = 0; l < 4; l++) {
        // replicate reference op-by-op (no fma contraction):
        float t1   = __fsub_rn(wv[l], wmin);
        float t2   = __fmul_rn(t1, s);
        float cond = __fadd_rn(t2, GMIN);
        float u    = __fsub_rn(cond, GMIN);
        float v    = __fdiv_rn(u, STEPQ);
        float q    = rintf(v);                       // round-half-even == jnp.round
        float cq   = __fadd_rn(__fmul_rn(q, STEPQ), GMIN);
        float inv  = __fdiv_rn(1.0f, cq);
        float rw   = (float)(2 * (513 + (j + l) - i)); // RP*((TS-i)+(j+1)), exact
        float ge   = __fdiv_rn(1.0f, __fadd_rn(inv, rw));
        pc[l] = cq; pg[l] = ge;
    }
    size_t sb = (size_t)t * 262144 + (size_t)i * 512 + j;
    *(float4*)&g_cond[sb] = oc;
    *(float4*)&g_geff[sb] = og;
}

// ---------------- kernel 3: per-(b,it) row sums of x ----------------
// grid (8, 1024), 128 threads
__global__ void k_xsum(const float* __restrict__ x) {
    int it = blockIdx.x, b = blockIdx.y, tid = threadIdx.x;
    float4 v = *(const float4*)&x[(size_t)b * 4096 + it * TSZ + tid * 4];
    float s = v.x + v.y + v.z + v.w;
    #pragma unroll
    for (int o = 16; o > 0; o >>= 1) s += __shfl_down_sync(0xffffffffu, s, o);
    __shared__ float sm[4];
    if ((tid & 31) == 0) sm[tid >> 5] = s;
    __syncthreads();
    if (tid == 0) g_xsum[b * ITN + it] = sm[0] + sm[1] + sm[2] + sm[3];
}

// ---------------- kernel 4: dual GEMM (currents = x@g_eff, ideal = x@cond) ----------------
// block tile 128x64, BK=16, 256 threads, per-thread 8x4 outputs x 2 matrices,
// accumulators as packed f32x2.
#define BM 128
#define BN 64
#define BK 16
__global__ void __launch_bounds__(256) k_gemm(const float* __restrict__ x) {
    int t  = blockIdx.z;          // tile id (it*8+ot)
    int it = t >> 3;
    int nb = blockIdx.x;          // 0..7
    int mb = blockIdx.y;          // 0..7
    int tid = threadIdx.x;
    int ty = tid >> 4;            // 0..15  (row group, 8 rows each)
    int tx = tid & 15;            // 0..15  (col group, 4 cols each)

    const float* A  = x + (size_t)mb * BM * 4096 + it * TSZ;          // [m][k], lda 4096
    const float* Bg = g_geff + (size_t)t * 262144 + (size_t)nb * BN;  // [k][n], ldb 512
    const float* Bc = g_cond + (size_t)t * 262144 + (size_t)nb * BN;

    __shared__ float As[BK][BM];
    __shared__ float Gs[BK][BN];
    __shared__ float Cs[BK][BN];

    ull accg[8][2], accc[8][2];
    #pragma unroll
    for (int m = 0; m < 8; m++) { accg[m][0] = 0; accg[m][1] = 0; accc[m][0] = 0; accc[m][1] = 0; }

    for (int kk = 0; kk < TSZ; kk += BK) {
        // load A tile (128x16), transposed into As[k][m]
        #pragma unroll
        for (int l = 0; l < 2; l++) {
            int lin = tid + l * 256;           // 0..511
            int row = lin >> 2;
            int k4  = (lin & 3) * 4;
            float4 v = *(const float4*)&A[(size_t)row * 4096 + kk + k4];
            As[k4 + 0][row] = v.x; As[k4 + 1][row] = v.y;
            As[k4 + 2][row] = v.z; As[k4 + 3][row] = v.w;
        }
        // load both B tiles (16x64)
        {
            int kr = tid >> 4;
            int n  = (tid & 15) * 4;
            *(float4*)&Gs[kr][n] = *(const float4*)&Bg[(size_t)(kk + kr) * 512 + n];
            *(float4*)&Cs[kr][n] = *(const float4*)&Bc[(size_t)(kk + kr) * 512 + n];
        }
        __syncthreads();

        #pragma unroll
        for (int k = 0; k < BK; k++) {
            float4 bg4 = *(const float4*)&Gs[k][tx * 4];
            float4 bc4 = *(const float4*)&Cs[k][tx * 4];
            ull bg0 = pk2(bg4.x, bg4.y), bg1 = pk2(bg4.z, bg4.w);
            ull bc0 = pk2(bc4.x, bc4.y), bc1 = pk2(bc4.z, bc4.w);
            float4 a0 = *(const float4*)&As[k][ty * 8];
            float4 a1 = *(const float4*)&As[k][ty * 8 + 4];
            float am[8] = { a0.x, a0.y, a0.z, a0.w, a1.x, a1.y, a1.z, a1.w };
            #pragma unroll
            for (int m = 0; m < 8; m++) {
                ull a2 = pk2(am[m], am[m]);
                fma2(accg[m][0], a2, bg0);
                fma2(accg[m][1], a2, bg1);
                fma2(accc[m][0], a2, bc0);
                fma2(accc[m][1], a2, bc1);
            }
        }
        __syncthreads();
    }

    size_t outbase = ((size_t)t * NB + (size_t)mb * BM) * TSZ + (size_t)nb * BN;
    #pragma unroll
    for (int m = 0; m < 8; m++) {
        float2 g0 = up2(accg[m][0]), g1 = up2(accg[m][1]);
        float2 c0 = up2(accc[m][0]), c1 = up2(accc[m][1]);
        size_t o = outbase + (size_t)(ty * 8 + m) * TSZ + tx * 4;
        *(float4*)&g_cur[o] = make_float4(g0.x, g0.y, g1.x, g1.y);
        *(float4*)&g_idl[o] = make_float4(c0.x, c0.y, c1.x, c1.y);
    }
}

// ---------------- kernel 5: stats + correction + unmap + sum over it + bias ----------------
// grid (ot=8, b=1024), 512 threads (one per output column of the tile)
__global__ void k_combine(const float* __restrict__ bias, float* __restrict__ out) {
    int ot = blockIdx.x, b = blockIdx.y, j = threadIdx.x;
    __shared__ float red[16][6];
    __shared__ float bc[6];
    float acc = 0.0f;

    for (int it = 0; it < ITN; it++) {
        int t = it * 8 + ot;
        size_t base = ((size_t)t * NB + b) * TSZ + j;
        float cur = g_cur[base];
        float idl = g_idl[base];

        float sc = cur, mxc = cur, mnc = cur;
        float si = idl, mxi = idl, mni = idl;
        #pragma unroll
        for (int o = 16; o > 0; o >>= 1) {
            sc  += __shfl_down_sync(0xffffffffu, sc, o);
            mxc  = fmaxf(mxc, __shfl_down_sync(0xffffffffu, mxc, o));
            mnc  = fminf(mnc, __shfl_down_sync(0xffffffffu, mnc, o));
            si  += __shfl_down_sync(0xffffffffu, si, o);
            mxi  = fmaxf(mxi, __shfl_down_sync(0xffffffffu, mxi, o));
            mni  = fminf(mni, __shfl_down_sync(0xffffffffu, mni, o));
        }
        if ((j & 31) == 0) {
            int w = j >> 5;
            red[w][0] = sc;  red[w][1] = mxc; red[w][2] = mnc;
            red[w][3] = si;  red[w][4] = mxi; red[w][5] = mni;
        }
        __syncthreads();
        if (j < 32) {
            bool v = j < 16;
            float a0 = v ? red[j][0] : 0.0f;
            float a1 = v ? red[j][1] : -3.402823466e38f;
            float a2 = v ? red[j][2] :  3.402823466e38f;
            float a3 = v ? red[j][3] : 0.0f;
            float a4 = v ? red[j][4] : -3.402823466e38f;
            float a5 = v ? red[j][5] :  3.402823466e38f;
            #pragma unroll
            for (int o = 8; o > 0; o >>= 1) {
                a0 += __shfl_down_sync(0xffffffffu, a0, o);
                a1  = fmaxf(a1, __shfl_down_sync(0xffffffffu, a1, o));
                a2  = fminf(a2, __shfl_down_sync(0xffffffffu, a2, o));
                a3 += __shfl_down_sync(0xffffffffu, a3, o);
                a4  = fmaxf(a4, __shfl_down_sync(0xffffffffu, a4, o));
                a5  = fminf(a5, __shfl_down_sync(0xffffffffu, a5, o));
            }
            if (j == 0) {
                bc[0] = a0; bc[1] = a1; bc[2] = a2;
                bc[3] = a3; bc[4] = a4; bc[5] = a5;
            }
        }
        __syncthreads();

        float cmean = bc[0] * (1.0f / 512.0f);   // exact /512
        float imean = bc[3] * (1.0f / 512.0f);
        float coeff = __fdiv_rn(__fsub_rn(bc[4], bc[5]),
                                __fadd_rn(__fsub_rn(bc[1], bc[2]), 1e-8f));
        float s = g_s[t], wmin = g_wmin[t];
        float off = __fmul_rn(g_xsum[b * ITN + it],
                              __fsub_rn(GMIN, __fmul_rn(s, wmin)));
        float val = __fadd_rn(__fmul_rn(__fsub_rn(cur, cmean), coeff), imean);
        acc += __fdiv_rn(__fsub_rn(val, off), s);
    }

    out[(size_t)b * 4096 + ot * TSZ + j] = __fadd_rn(acc, bias[ot * TSZ + j]);
}

// ---------------- launch ----------------
extern "C" void kernel_launch(void* const* d_in, const int* in_sizes, int n_in,
                              void* d_out, int out_size) {
    const float* x = nullptr; const float* w = nullptr; const float* bias = nullptr;
    for (int i = 0; i < n_in; i++) {
        if (in_sizes[i] == 1024 * 4096)      x    = (const float*)d_in[i];
        else if (in_sizes[i] == 4096 * 4096) w    = (const float*)d_in[i];
        else if (in_sizes[i] == 4096)        bias = (const float*)d_in[i];
    }
    float* out = (float*)d_out;

    k_minmax_part<<<dim3(8, 64), 256>>>(w);
    k_minmax_fin<<<1, 64>>>();
    k_build<<<16384, 256>>>(w);
    k_xsum<<<dim3(8, 1024), 128>>>(x);
    k_gemm<<<dim3(8, 8, 64), 256>>>(x);
    k_combine<<<dim3(8, 1024), 512>>>(bias, out);
}

// round 3
// speedup vs baseline: 2.0655x; 2.0655x over previous
#include <cuda_runtime.h>
#include <cuda_bf16.h>
#include <cstdint>

// ---------------- problem constants ----------------
#define TSZ   512
#define NTILE 64
#define ITN   8

#define GMIN   1e-6f
#define GDIFF  ((float)(1.0e-4 - 1.0e-6))
#define STEPQ  ((float)((1.0e-4 - 1.0e-6) / 15.0))
#define FINF   3.402823466e38f

typedef unsigned int uint32;
typedef unsigned long long ull;

// ---------------- scratch (static device memory) ----------------
__device__ __nv_bfloat16 g_xh[(size_t)1024 * 4096];
__device__ __nv_bfloat16 g_xl[(size_t)1024 * 4096];
__device__ __nv_bfloat16 g_Gh[(size_t)NTILE * TSZ * TSZ];   // geff hi, [t][n][k]
__device__ __nv_bfloat16 g_Gl[(size_t)NTILE * TSZ * TSZ];   // geff lo
__device__ __nv_bfloat16 g_Qi[(size_t)NTILE * TSZ * TSZ];   // quant code 0..15, [t][n][k]
__device__ float g_cur [(size_t)NTILE * 1024 * TSZ];        // 128 MB
__device__ float g_part[(size_t)NTILE * 4 * 1024 * 6];      // [t][nb][b][6]
__device__ float g_s[NTILE], g_wmin[NTILE];
__device__ float g_pmin[NTILE * 8], g_pmax[NTILE * 8];
__device__ float g_xsum[1024 * ITN];

// ---------------- PTX helpers ----------------
__device__ __forceinline__ uint32 smem_u32(const void* p) {
    uint32 a;
    asm("{ .reg .u64 t; cvta.to.shared.u64 t, %1; cvt.u32.u64 %0, t; }" : "=r"(a) : "l"(p));
    return a;
}
__device__ __forceinline__ void cpa16(uint32 dst, const void* src) {
    asm volatile("cp.async.cg.shared.global [%0], [%1], 16;" :: "r"(dst), "l"(src));
}
__device__ __forceinline__ void ldm_x4(uint32* r, uint32 addr) {
    asm volatile("ldmatrix.sync.aligned.m8n8.x4.shared.b16 {%0,%1,%2,%3}, [%4];"
                 : "=r"(r[0]), "=r"(r[1]), "=r"(r[2]), "=r"(r[3]) : "r"(addr));
}
__device__ __forceinline__ void mma16816(float* c, const uint32* a, const uint32* b) {
    asm volatile(
        "mma.sync.aligned.m16n8k16.row.col.f32.bf16.bf16.f32 "
        "{%0,%1,%2,%3}, {%4,%5,%6,%7}, {%8,%9}, {%0,%1,%2,%3};"
        : "+f"(c[0]), "+f"(c[1]), "+f"(c[2]), "+f"(c[3])
        : "r"(a[0]), "r"(a[1]), "r"(a[2]), "r"(a[3]), "r"(b[0]), "r"(b[1]));
}

// ---------------- kernel 1a: per-tile min/max partials ----------------
__global__ void k_minmax_part(const float* __restrict__ w) {
    int t = blockIdx.y, chunk = blockIdx.x;
    int it = t >> 3, ot = t & 7;
    int tid = threadIdx.x;
    float mn = FINF, mx = -FINF;
    int base = chunk * 32768 + tid;
    #pragma unroll 4
    for (int k = 0; k < 128; k++) {
        int e = base + k * 256;
        int i = e >> 9, j = e & 511;
        float v = w[(size_t)(it * TSZ + i) * 4096 + ot * TSZ + j];
        mn = fminf(mn, v); mx = fmaxf(mx, v);
    }
    __shared__ float smn[256], smx[256];
    smn[tid] = mn; smx[tid] = mx;
    __syncthreads();
    for (int o = 128; o > 0; o >>= 1) {
        if (tid < o) {
            smn[tid] = fminf(smn[tid], smn[tid + o]);
            smx[tid] = fmaxf(smx[tid], smx[tid + o]);
        }
        __syncthreads();
    }
    if (tid == 0) { g_pmin[t * 8 + chunk] = smn[0]; g_pmax[t * 8 + chunk] = smx[0]; }
}

__global__ void k_minmax_fin() {
    int t = threadIdx.x;
    if (t < NTILE) {
        float mn = g_pmin[t * 8], mx = g_pmax[t * 8];
        #pragma unroll
        for (int c = 1; c < 8; c++) {
            mn = fminf(mn, g_pmin[t * 8 + c]);
            mx = fmaxf(mx, g_pmax[t * 8 + c]);
        }
        float denom = __fadd_rn(__fsub_rn(mx, mn), 1e-12f);
        g_s[t] = __fdiv_rn(GDIFF, denom);
        g_wmin[t] = mn;
    }
}

// ---------------- kernel 2: build Gh/Gl/Qi, TRANSPOSED [t][n][k], bit-exact quant ----------------
__global__ void __launch_bounds__(256) k_build(const float* __restrict__ w) {
    __shared__ __nv_bfloat16 sGh[64][72], sGl[64][72], sQi[64][72];
    int sub = blockIdx.x, t = blockIdx.y;
    int it = t >> 3, ot = t & 7;
    int ib = sub >> 3, jb = sub & 7;     // ib: k-block, jb: n-block
    int i0 = ib * 64, j0 = jb * 64;
    int tid = threadIdx.x;
    float s = g_s[t], wmin = g_wmin[t];

    #pragma unroll
    for (int iter = 0; iter < 16; iter++) {
        int e = iter * 256 + tid;
        int i = e >> 6, j = e & 63;       // i: k, j: n
        float v = w[(size_t)(it * TSZ + i0 + i) * 4096 + ot * TSZ + j0 + j];
        // bit-exact reference op sequence:
        float t1   = __fsub_rn(v, wmin);
        float t2   = __fmul_rn(t1, s);
        float cond = __fadd_rn(t2, GMIN);
        float u    = __fsub_rn(cond, GMIN);
        float vv   = __fdiv_rn(u, STEPQ);
        float q    = rintf(vv);                       // 0..15, exact in bf16
        float cq   = __fadd_rn(__fmul_rn(q, STEPQ), GMIN);
        float inv  = __fdiv_rn(1.0f, cq);
        float rw   = (float)(2 * (513 + (j0 + j) - (i0 + i)));
        float ge   = __fdiv_rn(1.0f, __fadd_rn(inv, rw));
        __nv_bfloat16 gh = __float2bfloat16(ge);
        __nv_bfloat16 gl = __float2bfloat16(__fsub_rn(ge, __bfloat162float(gh)));
        sGh[j][i] = gh; sGl[j][i] = gl; sQi[j][i] = __float2bfloat16(q);
    }
    __syncthreads();

    size_t obase = (size_t)t * 262144 + (size_t)j0 * 512 + i0;
    #pragma unroll
    for (int iter = 0; iter < 2; iter++) {
        int L = iter * 256 + tid;
        int n = L >> 3, k8 = (L & 7) * 8;
        size_t o = obase + (size_t)n * 512 + k8;
        *(uint4*)&g_Gh[o] = *(const uint4*)&sGh[n][k8];
        *(uint4*)&g_Gl[o] = *(const uint4*)&sGl[n][k8];
        *(uint4*)&g_Qi[o] = *(const uint4*)&sQi[n][k8];
    }
}

// ---------------- kernel 2b: split x into bf16 hi/lo ----------------
__global__ void k_xsplit(const float* __restrict__ x) {
    int e = (blockIdx.x * 256 + threadIdx.x) * 4;
    float4 v = *(const float4*)&x[e];
    float vs[4] = { v.x, v.y, v.z, v.w };
    __nv_bfloat16 h[4], l[4];
    #pragma unroll
    for (int i = 0; i < 4; i++) {
        h[i] = __float2bfloat16(vs[i]);
        l[i] = __float2bfloat16(__fsub_rn(vs[i], __bfloat162float(h[i])));
    }
    *(ull*)&g_xh[e] = *(const ull*)h;
    *(ull*)&g_xl[e] = *(const ull*)l;
}

// ---------------- kernel 3: per-(b,it) row sums of x ----------------
__global__ void k_xsum(const float* __restrict__ x) {
    int it = blockIdx.x, b = blockIdx.y, tid = threadIdx.x;
    float4 v = *(const float4*)&x[(size_t)b * 4096 + it * TSZ + tid * 4];
    float s = v.x + v.y + v.z + v.w;
    #pragma unroll
    for (int o = 16; o > 0; o >>= 1) s += __shfl_down_sync(0xffffffffu, s, o);
    __shared__ float sm[4];
    if ((tid & 31) == 0) sm[tid >> 5] = s;
    __syncthreads();
    if (tid == 0) g_xsum[b * ITN + it] = sm[0] + sm[1] + sm[2] + sm[3];
}

// ---------------- kernel 4: mma.sync dual GEMM ----------------
// grid (nb=4, mb=8, t=64), 256 threads. CTA tile 128(M)x128(N), K=512.
// smem per stage: Ah,Al,Gh,Gl,Qi each 128 rows x 80B pitch (32 bf16 + pad).
#define PITCH 80
#define ARR   10240
#define OFF_AH 0
#define OFF_AL 10240
#define OFF_GH 20480
#define OFF_GL 30720
#define OFF_QI 40960
#define STAGE 51200
#define SMEM_GEMM (2 * STAGE)

__global__ void __launch_bounds__(256, 1) k_gemm() {
    extern __shared__ char smem[];
    uint32 sb = smem_u32(smem);
    int tid = threadIdx.x;
    int nb = blockIdx.x, mb = blockIdx.y, t = blockIdx.z;
    int it = t >> 3;

    const __nv_bfloat16* Ah = g_xh + (size_t)(mb * 128) * 4096 + it * 512;
    const __nv_bfloat16* Al = g_xl + (size_t)(mb * 128) * 4096 + it * 512;
    size_t bbase = (size_t)t * 262144 + (size_t)(nb * 128) * 512;
    const __nv_bfloat16* Bh = g_Gh + bbase;
    const __nv_bfloat16* Bl = g_Gl + bbase;
    const __nv_bfloat16* Bq = g_Qi + bbase;

    float acc_c[4][4][4];
    float acc_i[4][4][4];
    #pragma unroll
    for (int i = 0; i < 4; i++)
        #pragma unroll
        for (int j = 0; j < 4; j++)
            #pragma unroll
            for (int r = 0; r < 4; r++) { acc_c[i][j][r] = 0.f; acc_i[i][j][r] = 0.f; }

    auto issue = [&](int c) {
        uint32 sbuf = sb + (c & 1) * STAGE;
        int kk = c * 32;
        #pragma unroll
        for (int L0 = 0; L0 < 2; L0++) {
            int L = L0 * 256 + tid;
            int r = L >> 2, ch = L & 3;
            uint32 d = sbuf + r * PITCH + ch * 16;
            int soA = r * 4096 + kk + ch * 8;
            int soB = r * 512  + kk + ch * 8;
            cpa16(d + OFF_AH, Ah + soA);
            cpa16(d + OFF_AL, Al + soA);
            cpa16(d + OFF_GH, Bh + soB);
            cpa16(d + OFF_GL, Bl + soB);
            cpa16(d + OFF_QI, Bq + soB);
        }
        asm volatile("cp.async.commit_group;");
    };

    int lane = tid & 31, wid = tid >> 5;
    int wm0 = (wid >> 2) * 64, wn0 = (wid & 3) * 32;
    int wnid = wid & 3;
    int a_row = lane & 15;
    int a_koff = ((lane >> 4) & 1) * 16;
    int b_row = ((lane >> 4) & 1) * 8 + (lane & 7);
    int b_koff = ((lane >> 3) & 1) * 16;

    issue(0);
    for (int c = 0; c < 16; c++) {
        if (c < 15) {
            issue(c + 1);
            asm volatile("cp.async.wait_group 1;" ::: "memory");
        } else {
            asm volatile("cp.async.wait_group 0;" ::: "memory");
        }
        __syncthreads();
        uint32 sbuf = sb + (c & 1) * STAGE;

        #pragma unroll
        for (int ks = 0; ks < 2; ks++) {
            uint32 kb = ks * 32;
            uint32 ah[4][4], al[4][4];
            #pragma unroll
            for (int i = 0; i < 4; i++) {
                uint32 ad = sbuf + (uint32)(wm0 + i * 16 + a_row) * PITCH + kb + a_koff;
                ldm_x4(ah[i], ad + OFF_AH);
                ldm_x4(al[i], ad + OFF_AL);
            }
            uint32 gh[4][2], gl[4][2], qi[4][2];
            #pragma unroll
            for (int j2 = 0; j2 < 2; j2++) {
                uint32 bd = sbuf + (uint32)(wn0 + j2 * 16 + b_row) * PITCH + kb + b_koff;
                uint32 r4[4];
                ldm_x4(r4, bd + OFF_GH);
                gh[2*j2][0] = r4[0]; gh[2*j2][1] = r4[1];
                gh[2*j2+1][0] = r4[2]; gh[2*j2+1][1] = r4[3];
                ldm_x4(r4, bd + OFF_GL);
                gl[2*j2][0] = r4[0]; gl[2*j2][1] = r4[1];
                gl[2*j2+1][0] = r4[2]; gl[2*j2+1][1] = r4[3];
                ldm_x4(r4, bd + OFF_QI);
                qi[2*j2][0] = r4[0]; qi[2*j2][1] = r4[1];
                qi[2*j2+1][0] = r4[2]; qi[2*j2+1][1] = r4[3];
            }
            #pragma unroll
            for (int i = 0; i < 4; i++)
                #pragma unroll
                for (int j = 0; j < 4; j++) {
                    mma16816(acc_c[i][j], ah[i], gh[j]);
                    mma16816(acc_c[i][j], al[i], gh[j]);
                    mma16816(acc_c[i][j], ah[i], gl[j]);
                    mma16816(acc_i[i][j], ah[i], qi[j]);
                    mma16816(acc_i[i][j], al[i], qi[j]);
                }
        }
        __syncthreads();
    }

    // ---- epilogue: store currents, per-row stats of both accumulators ----
    int grp = lane >> 2, qd = lane & 3;
    size_t rowbase = (size_t)t * 1024 + (size_t)mb * 128;
    #pragma unroll
    for (int i = 0; i < 4; i++)
        #pragma unroll
        for (int h = 0; h < 2; h++) {
            int r = wm0 + i * 16 + h * 8 + grp;
            size_t gbb = (rowbase + r) * 512 + nb * 128 + wn0 + qd * 2;
            #pragma unroll
            for (int j = 0; j < 4; j++) {
                float2 v = make_float2(acc_c[i][j][2*h], acc_c[i][j][2*h+1]);
                *(float2*)&g_cur[gbb + j * 8] = v;
            }
        }

    float* stats = (float*)smem;   // [128 rows][4 nwarps][6]
    #pragma unroll
    for (int i = 0; i < 4; i++)
        #pragma unroll
        for (int h = 0; h < 2; h++) {
            float cs = 0.f, cmx = -FINF, cmn = FINF;
            float is_ = 0.f, imx = -FINF, imn = FINF;
            #pragma unroll
            for (int j = 0; j < 4; j++) {
                float v0 = acc_c[i][j][2*h], v1 = acc_c[i][j][2*h+1];
                cs += v0 + v1; cmx = fmaxf(cmx, fmaxf(v0, v1)); cmn = fminf(cmn, fminf(v0, v1));
                float u0 = acc_i[i][j][2*h], u1 = acc_i[i][j][2*h+1];
                is_ += u0 + u1; imx = fmaxf(imx, fmaxf(u0, u1)); imn = fminf(imn, fminf(u0, u1));
            }
            #pragma unroll
            for (int o = 1; o <= 2; o <<= 1) {
                cs  += __shfl_xor_sync(0xffffffffu, cs, o);
                cmx  = fmaxf(cmx, __shfl_xor_sync(0xffffffffu, cmx, o));
                cmn  = fminf(cmn, __shfl_xor_sync(0xffffffffu, cmn, o));
                is_ += __shfl_xor_sync(0xffffffffu, is_, o);
                imx  = fmaxf(imx, __shfl_xor_sync(0xffffffffu, imx, o));
                imn  = fminf(imn, __shfl_xor_sync(0xffffffffu, imn, o));
            }
            if (qd == 0) {
                int r = wm0 + i * 16 + h * 8 + grp;
                float* p = &stats[(r * 4 + wnid) * 6];
                p[0] = cs; p[1] = cmx; p[2] = cmn; p[3] = is_; p[4] = imx; p[5] = imn;
            }
        }
    __syncthreads();
    if (tid < 128) {
        float cs = 0.f, cmx = -FINF, cmn = FINF;
        float is_ = 0.f, imx = -FINF, imn = FINF;
        #pragma unroll
        for (int wn = 0; wn < 4; wn++) {
            const float* p = &stats[(tid * 4 + wn) * 6];
            cs += p[0]; cmx = fmaxf(cmx, p[1]); cmn = fminf(cmn, p[2]);
            is_ += p[3]; imx = fmaxf(imx, p[4]); imn = fminf(imn, p[5]);
        }
        float* p = &g_part[(((size_t)t * 4 + nb) * 1024 + (mb * 128 + tid)) * 6];
        p[0] = cs; p[1] = cmx; p[2] = cmn; p[3] = is_; p[4] = imx; p[5] = imn;
    }
}

// ---------------- kernel 5: combine ----------------
__global__ void __launch_bounds__(512) k_combine(const float* __restrict__ bias,
                                                 float* __restrict__ out) {
    int ot = blockIdx.x, b = blockIdx.y, j = threadIdx.x;
    float acc = 0.0f;
    #pragma unroll
    for (int it = 0; it < ITN; it++) {
        int t = it * 8 + ot;
        float cs = 0.f, cmx = -FINF, cmn = FINF, as_ = 0.f, amx = -FINF, amn = FINF;
        #pragma unroll
        for (int nb = 0; nb < 4; nb++) {
            const float* p = &g_part[(((size_t)t * 4 + nb) * 1024 + b) * 6];
            cs += p[0]; cmx = fmaxf(cmx, p[1]); cmn = fminf(cmn, p[2]);
            as_ += p[3]; amx = fmaxf(amx, p[4]); amn = fminf(amn, p[5]);
        }
        float cur = g_cur[((size_t)t * 1024 + b) * 512 + j];
        float xs = g_xsum[b * ITN + it];
        // ideal = STEPQ * a + GMIN * xs  (monotone transform of raw accumulator a)
        float cmean = cs * (1.0f / 512.0f);
        float imean = __fmul_rn(STEPQ, as_ * (1.0f / 512.0f)) + __fmul_rn(GMIN, xs);
        float coeff = __fdiv_rn(__fmul_rn(STEPQ, __fsub_rn(amx, amn)),
                                __fadd_rn(__fsub_rn(cmx, cmn), 1e-8f));
        float s = g_s[t], wmin = g_wmin[t];
        float off = __fmul_rn(xs, __fsub_rn(GMIN, __fmul_rn(s, wmin)));
        float val = __fadd_rn(__fmul_rn(__fsub_rn(cur, cmean), coeff), imean);
        acc += __fdiv_rn(__fsub_rn(val, off), s);
    }
    out[(size_t)b * 4096 + ot * TSZ + j] = __fadd_rn(acc, bias[ot * TSZ + j]);
}

// ---------------- launch ----------------
extern "C" void kernel_launch(void* const* d_in, const int* in_sizes, int n_in,
                              void* d_out, int out_size) {
    const float* x = nullptr; const float* w = nullptr; const float* bias = nullptr;
    for (int i = 0; i < n_in; i++) {
        if (in_sizes[i] == 1024 * 4096)      x    = (const float*)d_in[i];
        else if (in_sizes[i] == 4096 * 4096) w    = (const float*)d_in[i];
        else if (in_sizes[i] == 4096)        bias = (const float*)d_in[i];
    }
    float* out = (float*)d_out;

    cudaFuncSetAttribute(k_gemm, cudaFuncAttributeMaxDynamicSharedMemorySize, SMEM_GEMM);

    k_minmax_part<<<dim3(8, 64), 256>>>(w);
    k_minmax_fin<<<1, 64>>>();
    k_build<<<dim3(64, 64), 256>>>(w);
    k_xsplit<<<4096, 256>>>(x);
    k_xsum<<<dim3(8, 1024), 128>>>(x);
    k_gemm<<<dim3(4, 8, 64), 256, SMEM_GEMM>>>();
    k_combine<<<dim3(8, 1024), 512>>>(bias, out);
}

// round 4
// speedup vs baseline: 2.5619x; 1.2403x over previous
#include <cuda_runtime.h>
#include <cuda_bf16.h>
#include <cuda_fp16.h>
#include <cstdint>

// ---------------- problem constants ----------------
#define TSZ   512
#define NTILE 64
#define ITN   8

#define GMIN   1e-6f
#define GDIFF  ((float)(1.0e-4 - 1.0e-6))
#define STEPQ  ((float)((1.0e-4 - 1.0e-6) / 15.0))
#define FINF   3.402823466e38f
#define GSCALE 8192.0f
#define GINV   (1.0f / 8192.0f)

typedef unsigned int uint32;
typedef unsigned long long ull;

// ---------------- scratch (static device memory) ----------------
__device__ __half g_x16[(size_t)1024 * 4096];
__device__ __half g_Gh[(size_t)NTILE * TSZ * TSZ];   // geff*8192 hi, [t][n][k]
__device__ __half g_Gl[(size_t)NTILE * TSZ * TSZ];   // geff*8192 lo
__device__ __half g_Qi[(size_t)NTILE * TSZ * TSZ];   // quant code 0..15
__device__ float g_cur [(size_t)NTILE * 1024 * TSZ];  // 128 MB
__device__ float g_part[(size_t)NTILE * 4 * 1024 * 6];
__device__ float g_s[NTILE], g_wmin[NTILE];
__device__ float g_pmin[NTILE * 8], g_pmax[NTILE * 8];
__device__ float g_xsum[1024 * ITN];

// ---------------- PTX helpers ----------------
__device__ __forceinline__ uint32 smem_u32(const void* p) {
    uint32 a;
    asm("{ .reg .u64 t; cvta.to.shared.u64 t, %1; cvt.u32.u64 %0, t; }" : "=r"(a) : "l"(p));
    return a;
}
__device__ __forceinline__ void cpa16(uint32 dst, const void* src) {
    asm volatile("cp.async.cg.shared.global [%0], [%1], 16;" :: "r"(dst), "l"(src));
}
__device__ __forceinline__ void ldm_x4(uint32* r, uint32 addr) {
    asm volatile("ldmatrix.sync.aligned.m8n8.x4.shared.b16 {%0,%1,%2,%3}, [%4];"
                 : "=r"(r[0]), "=r"(r[1]), "=r"(r[2]), "=r"(r[3]) : "r"(addr));
}
__device__ __forceinline__ void mma16816(float* c, const uint32* a, const uint32* b) {
    asm volatile(
        "mma.sync.aligned.m16n8k16.row.col.f32.f16.f16.f32 "
        "{%0,%1,%2,%3}, {%4,%5,%6,%7}, {%8,%9}, {%0,%1,%2,%3};"
        : "+f"(c[0]), "+f"(c[1]), "+f"(c[2]), "+f"(c[3])
        : "r"(a[0]), "r"(a[1]), "r"(a[2]), "r"(a[3]), "r"(b[0]), "r"(b[1]));
}

// ---------------- kernel 1a: per-tile min/max partials ----------------
__global__ void k_minmax_part(const float* __restrict__ w) {
    int t = blockIdx.y, chunk = blockIdx.x;
    int it = t >> 3, ot = t & 7;
    int tid = threadIdx.x;
    float mn = FINF, mx = -FINF;
    int base = chunk * 32768 + tid;
    #pragma unroll 4
    for (int k = 0; k < 128; k++) {
        int e = base + k * 256;
        int i = e >> 9, j = e & 511;
        float v = w[(size_t)(it * TSZ + i) * 4096 + ot * TSZ + j];
        mn = fminf(mn, v); mx = fmaxf(mx, v);
    }
    __shared__ float smn[256], smx[256];
    smn[tid] = mn; smx[tid] = mx;
    __syncthreads();
    for (int o = 128; o > 0; o >>= 1) {
        if (tid < o) {
            smn[tid] = fminf(smn[tid], smn[tid + o]);
            smx[tid] = fmaxf(smx[tid], smx[tid + o]);
        }
        __syncthreads();
    }
    if (tid == 0) { g_pmin[t * 8 + chunk] = smn[0]; g_pmax[t * 8 + chunk] = smx[0]; }
}

__global__ void k_minmax_fin() {
    int t = threadIdx.x;
    if (t < NTILE) {
        float mn = g_pmin[t * 8], mx = g_pmax[t * 8];
        #pragma unroll
        for (int c = 1; c < 8; c++) {
            mn = fminf(mn, g_pmin[t * 8 + c]);
            mx = fmaxf(mx, g_pmax[t * 8 + c]);
        }
        float denom = __fadd_rn(__fsub_rn(mx, mn), 1e-12f);
        g_s[t] = __fdiv_rn(GDIFF, denom);
        g_wmin[t] = mn;
    }
}

// ---------------- kernel 2: build Gh/Gl/Qi (fp16, scaled), TRANSPOSED [t][n][k] ----------------
__global__ void __launch_bounds__(256) k_build(const float* __restrict__ w) {
    __shared__ __half sGh[64][72], sGl[64][72], sQi[64][72];
    int sub = blockIdx.x, t = blockIdx.y;
    int it = t >> 3, ot = t & 7;
    int ib = sub >> 3, jb = sub & 7;
    int i0 = ib * 64, j0 = jb * 64;
    int tid = threadIdx.x;
    float s = g_s[t], wmin = g_wmin[t];

    #pragma unroll
    for (int iter = 0; iter < 16; iter++) {
        int e = iter * 256 + tid;
        int i = e >> 6, j = e & 63;       // i: k, j: n
        float v = w[(size_t)(it * TSZ + i0 + i) * 4096 + ot * TSZ + j0 + j];
        // bit-exact reference op sequence:
        float t1   = __fsub_rn(v, wmin);
        float t2   = __fmul_rn(t1, s);
        float cond = __fadd_rn(t2, GMIN);
        float u    = __fsub_rn(cond, GMIN);
        float vv   = __fdiv_rn(u, STEPQ);
        float q    = rintf(vv);                       // 0..15, exact in fp16
        float cq   = __fadd_rn(__fmul_rn(q, STEPQ), GMIN);
        float inv  = __fdiv_rn(1.0f, cq);
        float rw   = (float)(2 * (513 + (j0 + j) - (i0 + i)));
        float ge   = __fdiv_rn(1.0f, __fadd_rn(inv, rw));
        float gs   = ge * GSCALE;                     // exact pow2 scale
        __half gh  = __float2half_rn(gs);
        __half gl  = __float2half_rn(__fsub_rn(gs, __half2float(gh)));
        sGh[j][i] = gh; sGl[j][i] = gl; sQi[j][i] = __float2half_rn(q);
    }
    __syncthreads();

    size_t obase = (size_t)t * 262144 + (size_t)j0 * 512 + i0;
    #pragma unroll
    for (int iter = 0; iter < 2; iter++) {
        int L = iter * 256 + tid;
        int n = L >> 3, k8 = (L & 7) * 8;
        size_t o = obase + (size_t)n * 512 + k8;
        *(uint4*)&g_Gh[o] = *(const uint4*)&sGh[n][k8];
        *(uint4*)&g_Gl[o] = *(const uint4*)&sGl[n][k8];
        *(uint4*)&g_Qi[o] = *(const uint4*)&sQi[n][k8];
    }
}

// ---------------- kernel 2b: x -> fp16 + per-(b,it) row sums, fused ----------------
// grid (8192) = (b*8+it), 128 threads x 4 elems
__global__ void k_xprep(const float* __restrict__ x) {
    int blk = blockIdx.x;
    int b = blk >> 3, it = blk & 7;
    int tid = threadIdx.x;
    size_t base = (size_t)b * 4096 + it * TSZ + tid * 4;
    float4 v = *(const float4*)&x[base];
    __half h[4] = { __float2half_rn(v.x), __float2half_rn(v.y),
                    __float2half_rn(v.z), __float2half_rn(v.w) };
    *(ull*)&g_x16[base] = *(const ull*)h;
    float s = v.x + v.y + v.z + v.w;
    #pragma unroll
    for (int o = 16; o > 0; o >>= 1) s += __shfl_down_sync(0xffffffffu, s, o);
    __shared__ float sm[4];
    if ((tid & 31) == 0) sm[tid >> 5] = s;
    __syncthreads();
    if (tid == 0) g_xsum[b * ITN + it] = sm[0] + sm[1] + sm[2] + sm[3];
}

// ---------------- kernel 4: mma.sync dual GEMM (3 passes, fp16) ----------------
// grid (nb=4, mb=8, t=64), 256 threads. CTA tile 128x128, K=512, k-chunk 32.
#define PITCH 80
#define OFF_X  0
#define OFF_GH 10240
#define OFF_GL 20480
#define OFF_QI 30720
#define STAGE 40960
#define SMEM_GEMM (2 * STAGE)

__global__ void __launch_bounds__(256, 1) k_gemm() {
    extern __shared__ char smem[];
    uint32 sb = smem_u32(smem);
    int tid = threadIdx.x;
    int nb = blockIdx.x, mb = blockIdx.y, t = blockIdx.z;
    int it = t >> 3;

    const __half* Ax = g_x16 + (size_t)(mb * 128) * 4096 + it * 512;
    size_t bbase = (size_t)t * 262144 + (size_t)(nb * 128) * 512;
    const __half* Bh = g_Gh + bbase;
    const __half* Bl = g_Gl + bbase;
    const __half* Bq = g_Qi + bbase;

    float acc_c[4][4][4];
    float acc_i[4][4][4];
    #pragma unroll
    for (int i = 0; i < 4; i++)
        #pragma unroll
        for (int j = 0; j < 4; j++)
            #pragma unroll
            for (int r = 0; r < 4; r++) { acc_c[i][j][r] = 0.f; acc_i[i][j][r] = 0.f; }

    auto issue = [&](int c) {
        uint32 sbuf = sb + (c & 1) * STAGE;
        int kk = c * 32;
        #pragma unroll
        for (int L0 = 0; L0 < 2; L0++) {
            int L = L0 * 256 + tid;
            int r = L >> 2, ch = L & 3;
            uint32 d = sbuf + r * PITCH + ch * 16;
            int soA = r * 4096 + kk + ch * 8;
            int soB = r * 512  + kk + ch * 8;
            cpa16(d + OFF_X,  Ax + soA);
            cpa16(d + OFF_GH, Bh + soB);
            cpa16(d + OFF_GL, Bl + soB);
            cpa16(d + OFF_QI, Bq + soB);
        }
        asm volatile("cp.async.commit_group;");
    };

    int lane = tid & 31, wid = tid >> 5;
    int wm0 = (wid >> 2) * 64, wn0 = (wid & 3) * 32;
    int wnid = wid & 3;
    int a_row = lane & 15;
    int a_koff = ((lane >> 4) & 1) * 16;
    int b_row = ((lane >> 4) & 1) * 8 + (lane & 7);
    int b_koff = ((lane >> 3) & 1) * 16;

    issue(0);
    for (int c = 0; c < 16; c++) {
        if (c < 15) {
            issue(c + 1);
            asm volatile("cp.async.wait_group 1;" ::: "memory");
        } else {
            asm volatile("cp.async.wait_group 0;" ::: "memory");
        }
        __syncthreads();
        uint32 sbuf = sb + (c & 1) * STAGE;

        #pragma unroll
        for (int ks = 0; ks < 2; ks++) {
            uint32 kb = ks * 32;
            uint32 ax[4][4];
            #pragma unroll
            for (int i = 0; i < 4; i++) {
                uint32 ad = sbuf + (uint32)(wm0 + i * 16 + a_row) * PITCH + kb + a_koff;
                ldm_x4(ax[i], ad + OFF_X);
            }
            uint32 gh[4][2], gl[4][2], qi[4][2];
            #pragma unroll
            for (int j2 = 0; j2 < 2; j2++) {
                uint32 bd = sbuf + (uint32)(wn0 + j2 * 16 + b_row) * PITCH + kb + b_koff;
                uint32 r4[4];
                ldm_x4(r4, bd + OFF_GH);
                gh[2*j2][0] = r4[0]; gh[2*j2][1] = r4[1];
                gh[2*j2+1][0] = r4[2]; gh[2*j2+1][1] = r4[3];
                ldm_x4(r4, bd + OFF_GL);
                gl[2*j2][0] = r4[0]; gl[2*j2][1] = r4[1];
                gl[2*j2+1][0] = r4[2]; gl[2*j2+1][1] = r4[3];
                ldm_x4(r4, bd + OFF_QI);
                qi[2*j2][0] = r4[0]; qi[2*j2][1] = r4[1];
                qi[2*j2+1][0] = r4[2]; qi[2*j2+1][1] = r4[3];
            }
            #pragma unroll
            for (int i = 0; i < 4; i++)
                #pragma unroll
                for (int j = 0; j < 4; j++) {
                    mma16816(acc_c[i][j], ax[i], gh[j]);
                    mma16816(acc_c[i][j], ax[i], gl[j]);
                    mma16816(acc_i[i][j], ax[i], qi[j]);
                }
        }
        __syncthreads();
    }

    // ---- epilogue: rescale currents, store, per-row stats of both accs ----
    int grp = lane >> 2, qd = lane & 3;
    size_t rowbase = (size_t)t * 1024 + (size_t)mb * 128;
    #pragma unroll
    for (int i = 0; i < 4; i++)
        #pragma unroll
        for (int j = 0; j < 4; j++)
            #pragma unroll
            for (int r = 0; r < 4; r++) acc_c[i][j][r] *= GINV;

    #pragma unroll
    for (int i = 0; i < 4; i++)
        #pragma unroll
        for (int h = 0; h < 2; h++) {
            int r = wm0 + i * 16 + h * 8 + grp;
            size_t gbb = (rowbase + r) * 512 + nb * 128 + wn0 + qd * 2;
            #pragma unroll
            for (int j = 0; j < 4; j++)
                *(float2*)&g_cur[gbb + j * 8] =
                    make_float2(acc_c[i][j][2*h], acc_c[i][j][2*h+1]);
        }

    float* stats = (float*)smem;   // [128 rows][4 nwarps][6]
    #pragma unroll
    for (int i = 0; i < 4; i++)
        #pragma unroll
        for (int h = 0; h < 2; h++) {
            float cs = 0.f, cmx = -FINF, cmn = FINF;
            float is_ = 0.f, imx = -FINF, imn = FINF;
            #pragma unroll
            for (int j = 0; j < 4; j++) {
                float v0 = acc_c[i][j][2*h], v1 = acc_c[i][j][2*h+1];
                cs += v0 + v1; cmx = fmaxf(cmx, fmaxf(v0, v1)); cmn = fminf(cmn, fminf(v0, v1));
                float u0 = acc_i[i][j][2*h], u1 = acc_i[i][j][2*h+1];
                is_ += u0 + u1; imx = fmaxf(imx, fmaxf(u0, u1)); imn = fminf(imn, fminf(u0, u1));
            }
            #pragma unroll
            for (int o = 1; o <= 2; o <<= 1) {
                cs  += __shfl_xor_sync(0xffffffffu, cs, o);
                cmx  = fmaxf(cmx, __shfl_xor_sync(0xffffffffu, cmx, o));
                cmn  = fminf(cmn, __shfl_xor_sync(0xffffffffu, cmn, o));
                is_ += __shfl_xor_sync(0xffffffffu, is_, o);
                imx  = fmaxf(imx, __shfl_xor_sync(0xffffffffu, imx, o));
                imn  = fminf(imn, __shfl_xor_sync(0xffffffffu, imn, o));
            }
            if (qd == 0) {
                int r = wm0 + i * 16 + h * 8 + grp;
                float* p = &stats[(r * 4 + wnid) * 6];
                p[0] = cs; p[1] = cmx; p[2] = cmn; p[3] = is_; p[4] = imx; p[5] = imn;
            }
        }
    __syncthreads();
    if (tid < 128) {
        float cs = 0.f, cmx = -FINF, cmn = FINF;
        float is_ = 0.f, imx = -FINF, imn = FINF;
        #pragma unroll
        for (int wn = 0; wn < 4; wn++) {
            const float* p = &stats[(tid * 4 + wn) * 6];
            cs += p[0]; cmx = fmaxf(cmx, p[1]); cmn = fminf(cmn, p[2]);
            is_ += p[3]; imx = fmaxf(imx, p[4]); imn = fminf(imn, p[5]);
        }
        float* p = &g_part[(((size_t)t * 4 + nb) * 1024 + (mb * 128 + tid)) * 6];
        p[0] = cs; p[1] = cmx; p[2] = cmn; p[3] = is_; p[4] = imx; p[5] = imn;
    }
}

// ---------------- kernel 5: combine ----------------
__global__ void __launch_bounds__(512) k_combine(const float* __restrict__ bias,
                                                 float* __restrict__ out) {
    int ot = blockIdx.x, b = blockIdx.y, j = threadIdx.x;
    float acc = 0.0f;
    #pragma unroll
    for (int it = 0; it < ITN; it++) {
        int t = it * 8 + ot;
        float cs = 0.f, cmx = -FINF, cmn = FINF, as_ = 0.f, amx = -FINF, amn = FINF;
        #pragma unroll
        for (int nb = 0; nb < 4; nb++) {
            const float* p = &g_part[(((size_t)t * 4 + nb) * 1024 + b) * 6];
            cs += p[0]; cmx = fmaxf(cmx, p[1]); cmn = fminf(cmn, p[2]);
            as_ += p[3]; amx = fmaxf(amx, p[4]); amn = fminf(amn, p[5]);
        }
        float cur = g_cur[((size_t)t * 1024 + b) * 512 + j];
        float xs = g_xsum[b * ITN + it];
        // ideal = STEPQ * a + GMIN * xs (monotone transform of raw accumulator a)
        float cmean = cs * (1.0f / 512.0f);
        float imean = __fmul_rn(STEPQ, as_ * (1.0f / 512.0f)) + __fmul_rn(GMIN, xs);
        float coeff = __fdiv_rn(__fmul_rn(STEPQ, __fsub_rn(amx, amn)),
                                __fadd_rn(__fsub_rn(cmx, cmn), 1e-8f));
        float s = g_s[t], wmin = g_wmin[t];
        float off = __fmul_rn(xs, __fsub_rn(GMIN, __fmul_rn(s, wmin)));
        float val = __fadd_rn(__fmul_rn(__fsub_rn(cur, cmean), coeff), imean);
        acc += __fdiv_rn(__fsub_rn(val, off), s);
    }
    out[(size_t)b * 4096 + ot * TSZ + j] = __fadd_rn(acc, bias[ot * TSZ + j]);
}

// ---------------- launch ----------------
extern "C" void kernel_launch(void* const* d_in, const int* in_sizes, int n_in,
                              void* d_out, int out_size) {
    const float* x = nullptr; const float* w = nullptr; const float* bias = nullptr;
    for (int i = 0; i < n_in; i++) {
        if (in_sizes[i] == 1024 * 4096)      x    = (const float*)d_in[i];
        else if (in_sizes[i] == 4096 * 4096) w    = (const float*)d_in[i];
        else if (in_sizes[i] == 4096)        bias = (const float*)d_in[i];
    }
    float* out = (float*)d_out;

    cudaFuncSetAttribute(k_gemm, cudaFuncAttributeMaxDynamicSharedMemorySize, SMEM_GEMM);

    k_minmax_part<<<dim3(8, 64), 256>>>(w);
    k_minmax_fin<<<1, 64>>>();
    k_build<<<dim3(64, 64), 256>>>(w);
    k_xprep<<<8192, 128>>>(x);
    k_gemm<<<dim3(4, 8, 64), 256, SMEM_GEMM>>>();
    k_combine<<<dim3(8, 1024), 512>>>(bias, out);
}